// round 16
// baseline (speedup 1.0000x reference)
#include <cuda_runtime.h>
#include <cuda_fp16.h>
#include <cstdint>
#include <cstddef>

#define S_LEN   2048
#define D_MODEL 1024
#define H_NUM   16
#define DH      64
#define M_TOK   4096
#define QKV_LD  3072

// ---------------------------------------------------------------------------
// Device scratch (fp16 words)
// ---------------------------------------------------------------------------
__device__ uint16_t g_x_h   [(size_t)M_TOK * D_MODEL];
__device__ uint16_t g_wqkv_h[(size_t)QKV_LD * D_MODEL];
__device__ uint16_t g_qkv_h [(size_t)M_TOK * QKV_LD];
__device__ uint16_t g_ao_h  [(size_t)M_TOK * D_MODEL];
__device__ uint16_t g_wout_h[(size_t)D_MODEL * D_MODEL];

// ---------------------------------------------------------------------------
// PTX helpers
// ---------------------------------------------------------------------------
__device__ __forceinline__ uint32_t smem_u32(const void* p) {
    uint32_t a;
    asm("{ .reg .u64 t; cvta.to.shared.u64 t, %1; cvt.u32.u64 %0, t; }" : "=r"(a) : "l"(p));
    return a;
}
__device__ __forceinline__ void cp_async16(uint32_t dst, const void* src) {
    asm volatile("cp.async.cg.shared.global [%0], [%1], 16;" :: "r"(dst), "l"(src));
}
__device__ __forceinline__ void cp_commit() {
    asm volatile("cp.async.commit_group;" ::: "memory");
}
template <int N>
__device__ __forceinline__ void cp_wait() {
    asm volatile("cp.async.wait_group %0;" :: "n"(N) : "memory");
}
__device__ __forceinline__ void ldsm_x4(uint32_t& r0, uint32_t& r1, uint32_t& r2,
                                        uint32_t& r3, uint32_t a) {
    asm volatile("ldmatrix.sync.aligned.m8n8.x4.shared.b16 {%0,%1,%2,%3}, [%4];"
                 : "=r"(r0), "=r"(r1), "=r"(r2), "=r"(r3) : "r"(a));
}
__device__ __forceinline__ void ldsm_x4_t(uint32_t& r0, uint32_t& r1, uint32_t& r2,
                                          uint32_t& r3, uint32_t a) {
    asm volatile("ldmatrix.sync.aligned.m8n8.x4.trans.shared.b16 {%0,%1,%2,%3}, [%4];"
                 : "=r"(r0), "=r"(r1), "=r"(r2), "=r"(r3) : "r"(a));
}
__device__ __forceinline__ void mma_f16(float* d, const uint32_t* a, const uint32_t* b) {
    asm volatile("mma.sync.aligned.m16n8k16.row.col.f32.f16.f16.f32 "
                 "{%0,%1,%2,%3}, {%4,%5,%6,%7}, {%8,%9}, {%0,%1,%2,%3};"
                 : "+f"(d[0]), "+f"(d[1]), "+f"(d[2]), "+f"(d[3])
                 : "r"(a[0]), "r"(a[1]), "r"(a[2]), "r"(a[3]), "r"(b[0]), "r"(b[1]));
}
__device__ __forceinline__ uint32_t pack_pair_h(float a, float b) {
    return (uint32_t)__half_as_ushort(__float2half_rn(a)) |
           ((uint32_t)__half_as_ushort(__float2half_rn(b)) << 16);
}

// ---------------------------------------------------------------------------
// Packer
// ---------------------------------------------------------------------------
__global__ __launch_bounds__(256) void pack_h16(
    const float* __restrict__ in, uint16_t* __restrict__ hi, int n4)
{
    int i = blockIdx.x * 256 + threadIdx.x;
    if (i >= n4) return;
    float4 v = reinterpret_cast<const float4*>(in)[i];
    reinterpret_cast<uint2*>(hi)[i] =
        make_uint2(pack_pair_h(v.x, v.y), pack_pair_h(v.z, v.w));
}

// ---------------------------------------------------------------------------
// HMMA fp16 GEMM: C[M,N] = A @ B^T (+bias), single-pass fp16.
// CTA 128x128, BK=64, 4 warps (2x2), warp tile 64x64, 3-stage cp.async.
// smem: 3 stages x (A+B) x 18432 = 110592 B/CTA -> 2 CTAs/SM (221 KB, fits;
// regs 2 x 128 x 206 = 52.7K <= 64K).
// ---------------------------------------------------------------------------
#define BK        64
#define PAD_K     72
#define TILE_SMB  (128 * PAD_K * 2)      // 18432 B
#define STAGE_B   (2 * TILE_SMB)         // 36864 B
#define G_SMEM    (3 * STAGE_B)          // 110592 B

template <bool HAS_BIAS, bool SPLIT_OUT>
__global__ __launch_bounds__(128) void gemm_mma(
    const uint16_t* __restrict__ A, const uint16_t* __restrict__ B,
    const float* __restrict__ bias, float* __restrict__ C,
    uint16_t* __restrict__ Ch,
    int M, int N, int K)
{
    extern __shared__ char smem[];
    const uint32_t sb = smem_u32(smem);
    const int tid = threadIdx.x;
    const int wid = tid >> 5;
    const int lane = tid & 31;
    const int bm = blockIdx.y * 128;
    const int bn = blockIdx.x * 128;
    const int wm = wid >> 1;
    const int wn = wid & 1;
    const int nk = K / BK;

    const uint16_t* gA = A + (size_t)bm * K;
    const uint16_t* gB = B + (size_t)bn * K;

    auto load_tile = [&](uint32_t tb, const uint16_t* g, int k0) {
#pragma unroll
        for (int it = 0; it < 8; ++it) {
            int c = tid + it * 128;
            int r = c >> 3, col = (c & 7) * 8;
            cp_async16(tb + r * (PAD_K * 2) + col * 2, g + (size_t)r * K + k0 + col);
        }
    };
    auto load_stage = [&](int s, int k0) {
        uint32_t base = sb + s * STAGE_B;
        load_tile(base, gA, k0);
        load_tile(base + TILE_SMB, gB, k0);
        cp_commit();
    };

    float acc[4][8][4];
#pragma unroll
    for (int mt = 0; mt < 4; ++mt)
#pragma unroll
        for (int nt = 0; nt < 8; ++nt)
#pragma unroll
            for (int e = 0; e < 4; ++e) acc[mt][nt][e] = 0.f;

    const int lrow8 = lane & 7;
    const int lq    = lane >> 3;
    const int a_roff = lrow8 + (lq & 1) * 8;
    const int a_coff = (lq >> 1) * 8;
    const int b_noff = lrow8 + (lq >> 1) * 8;
    const int b_coff = (lq & 1) * 8;

    load_stage(0, 0);
    if (nk > 1) load_stage(1, BK);

    for (int i = 0; i < nk; ++i) {
        const int s = i % 3;
        if (i + 2 < nk) { load_stage((i + 2) % 3, (i + 2) * BK); cp_wait<2>(); }
        else if (i + 1 < nk) { cp_wait<1>(); }
        else { cp_wait<0>(); }
        __syncthreads();

        const uint32_t stg = sb + s * STAGE_B;
#pragma unroll
        for (int kk = 0; kk < BK; kk += 16) {
            uint32_t bh[8][2];
#pragma unroll
            for (int ntp = 0; ntp < 4; ++ntp) {
                int nidx = wn * 64 + ntp * 16 + b_noff;
                int cidx = kk + b_coff;
                ldsm_x4(bh[2 * ntp][0], bh[2 * ntp][1], bh[2 * ntp + 1][0], bh[2 * ntp + 1][1],
                        stg + TILE_SMB + (nidx * PAD_K + cidx) * 2);
            }
#pragma unroll
            for (int mt = 0; mt < 4; ++mt) {
                int midx = wm * 64 + mt * 16 + a_roff;
                int cidx = kk + a_coff;
                uint32_t ah[4];
                ldsm_x4(ah[0], ah[1], ah[2], ah[3], stg + (midx * PAD_K + cidx) * 2);
#pragma unroll
                for (int nt = 0; nt < 8; ++nt)
                    mma_f16(acc[mt][nt], ah, bh[nt]);
            }
        }
        __syncthreads();
    }

#pragma unroll
    for (int mt = 0; mt < 4; ++mt) {
#pragma unroll
        for (int nt = 0; nt < 8; ++nt) {
            int r = bm + wm * 64 + mt * 16 + (lane >> 2);
            int c = bn + wn * 64 + nt * 8 + (lane & 3) * 2;
            if (SPLIT_OUT) {
                *reinterpret_cast<uint32_t*>(&Ch[(size_t)r * N + c]) =
                    pack_pair_h(acc[mt][nt][0], acc[mt][nt][1]);
                *reinterpret_cast<uint32_t*>(&Ch[(size_t)(r + 8) * N + c]) =
                    pack_pair_h(acc[mt][nt][2], acc[mt][nt][3]);
            } else {
                float b0 = 0.f, b1 = 0.f;
                if (HAS_BIAS) { b0 = bias[c]; b1 = bias[c + 1]; }
                *reinterpret_cast<float2*>(&C[(size_t)r * N + c]) =
                    make_float2(acc[mt][nt][0] + b0, acc[mt][nt][1] + b1);
                *reinterpret_cast<float2*>(&C[(size_t)(r + 8) * N + c]) =
                    make_float2(acc[mt][nt][2] + b0, acc[mt][nt][3] + b1);
            }
        }
    }
}

// ---------------------------------------------------------------------------
// fp16 causal flash attention, 32 q-rows per warp.
// CTA: 128 q-rows x (b,h), 4 warps. Bc=64. 3-stage KV pipeline.
// Softmax in exp2 domain: scale folds 1/sqrt(dh) * log2(e).
// ---------------------------------------------------------------------------
#define ATT_PAD    72
#define ATT_ROWB   (ATT_PAD * 2)          // 144 B
#define KV_TILE_B  (64 * ATT_ROWB)        // 9216
#define ATT_STAGE  (2 * KV_TILE_B)        // 18432 (K, V)
#define ATT_SMEM   (3 * ATT_STAGE)        // 55296

#define SCALE_LOG2 (0.125f * 1.4426950408889634f)

__global__ __launch_bounds__(128) void flash_attn_mma(
    const uint16_t* __restrict__ qkv_h, uint16_t* __restrict__ ao_h)
{
    extern __shared__ char smem[];
    const uint32_t sb = smem_u32(smem);
    const int tid = threadIdx.x, wid = tid >> 5, lane = tid & 31;
    const int qb = 15 - blockIdx.x;
    const int bh = blockIdx.y;
    const int b = bh >> 4, h = bh & 15;
    const size_t tok0 = (size_t)b * S_LEN;

    const int lrow8 = lane & 7, lq = lane >> 3;
    const int a_roff = lrow8 + (lq & 1) * 8;
    const int a_coff = (lq >> 1) * 8;
    const int b_noff = lrow8 + (lq >> 1) * 8;
    const int b_coff = (lq & 1) * 8;
    const int v_roff = (lane & 7) + ((lane >> 3) & 1) * 8;
    const int v_coff = (lane >> 4) * 8;

    // ---- stage Q (128 rows x 64); pull both m-tiles to regs
    {
        const size_t qrow0 = tok0 + (size_t)qb * 128;
#pragma unroll
        for (int it = 0; it < 8; ++it) {
            int c = tid + it * 128;
            int r = c >> 3, col = (c & 7) * 8;
            cp_async16(sb + r * ATT_ROWB + col * 2,
                       qkv_h + (qrow0 + r) * QKV_LD + h * 192 + col);
        }
        cp_commit();
        cp_wait<0>();
        __syncthreads();
    }
    uint32_t qh[2][4][4];
#pragma unroll
    for (int mt = 0; mt < 2; ++mt)
#pragma unroll
        for (int j = 0; j < 4; ++j) {
            int rr = wid * 32 + mt * 16 + a_roff;
            int cc = j * 16 + a_coff;
            ldsm_x4(qh[mt][j][0], qh[mt][j][1], qh[mt][j][2], qh[mt][j][3],
                    sb + rr * ATT_ROWB + cc * 2);
        }
    __syncthreads();

    auto load_kv = [&](int s, int kb) {
        uint32_t base = sb + s * ATT_STAGE;
        const size_t krow0 = tok0 + (size_t)kb * 64;
        const int koff = h * 192 + 64, voff = h * 192 + 128;
#pragma unroll
        for (int it = 0; it < 4; ++it) {
            int c = tid + it * 128;
            int r = c >> 3, col = (c & 7) * 8;
            const size_t go = (krow0 + r) * QKV_LD + col;
            cp_async16(base + r * ATT_ROWB + col * 2, qkv_h + go + koff);
            cp_async16(base + KV_TILE_B + r * ATT_ROWB + col * 2, qkv_h + go + voff);
        }
        cp_commit();
    };

    float o[2][8][4];
#pragma unroll
    for (int mt = 0; mt < 2; ++mt)
#pragma unroll
        for (int nt = 0; nt < 8; ++nt)
#pragma unroll
            for (int e = 0; e < 4; ++e) o[mt][nt][e] = 0.f;
    float mx[2][2], lsum[2][2];
#pragma unroll
    for (int mt = 0; mt < 2; ++mt) {
        mx[mt][0] = -1e30f; mx[mt][1] = -1e30f;
        lsum[mt][0] = 0.f;  lsum[mt][1] = 0.f;
    }

    const int nkb = 2 * qb + 2;
    load_kv(0, 0);
    if (nkb > 1) load_kv(1, 1);

    for (int kb = 0; kb < nkb; ++kb) {
        const int s = kb % 3;
        if (kb + 2 < nkb) { load_kv((kb + 2) % 3, kb + 2); cp_wait<2>(); }
        else if (kb + 1 < nkb) { cp_wait<1>(); }
        else { cp_wait<0>(); }
        __syncthreads();
        const uint32_t kbase = sb + s * ATT_STAGE;

        float sc[2][8][4];
#pragma unroll
        for (int mt = 0; mt < 2; ++mt)
#pragma unroll
            for (int nt = 0; nt < 8; ++nt)
#pragma unroll
                for (int e = 0; e < 4; ++e) sc[mt][nt][e] = 0.f;

#pragma unroll
        for (int j = 0; j < 4; ++j) {
            uint32_t kf[8][2];
#pragma unroll
            for (int p = 0; p < 4; ++p) {
                int nn = p * 16 + b_noff;
                int cc = j * 16 + b_coff;
                ldsm_x4(kf[2 * p][0], kf[2 * p][1], kf[2 * p + 1][0], kf[2 * p + 1][1],
                        kbase + nn * ATT_ROWB + cc * 2);
            }
#pragma unroll
            for (int mt = 0; mt < 2; ++mt)
#pragma unroll
                for (int nt = 0; nt < 8; ++nt)
                    mma_f16(sc[mt][nt], qh[mt][j], kf[nt]);
        }

        // scale into log2 domain
#pragma unroll
        for (int mt = 0; mt < 2; ++mt)
#pragma unroll
            for (int nt = 0; nt < 8; ++nt)
#pragma unroll
                for (int e = 0; e < 4; ++e) sc[mt][nt][e] *= SCALE_LOG2;

        if (kb >= 2 * qb) {
#pragma unroll
            for (int mt = 0; mt < 2; ++mt) {
                const int gr0 = qb * 128 + wid * 32 + mt * 16 + (lane >> 2);
#pragma unroll
                for (int nt = 0; nt < 8; ++nt) {
                    int gc = kb * 64 + nt * 8 + (lane & 3) * 2;
                    if (gc     > gr0)     sc[mt][nt][0] = -1e30f;
                    if (gc + 1 > gr0)     sc[mt][nt][1] = -1e30f;
                    if (gc     > gr0 + 8) sc[mt][nt][2] = -1e30f;
                    if (gc + 1 > gr0 + 8) sc[mt][nt][3] = -1e30f;
                }
            }
        }

#pragma unroll
        for (int mt = 0; mt < 2; ++mt) {
            float mx0 = -1e30f, mx1 = -1e30f;
#pragma unroll
            for (int nt = 0; nt < 8; ++nt) {
                mx0 = fmaxf(mx0, fmaxf(sc[mt][nt][0], sc[mt][nt][1]));
                mx1 = fmaxf(mx1, fmaxf(sc[mt][nt][2], sc[mt][nt][3]));
            }
#pragma unroll
            for (int w = 1; w < 4; w <<= 1) {
                mx0 = fmaxf(mx0, __shfl_xor_sync(0xffffffffu, mx0, w));
                mx1 = fmaxf(mx1, __shfl_xor_sync(0xffffffffu, mx1, w));
            }
            float mn0 = fmaxf(mx[mt][0], mx0), mn1 = fmaxf(mx[mt][1], mx1);
            float c0 = exp2f(mx[mt][0] - mn0), c1 = exp2f(mx[mt][1] - mn1);
            mx[mt][0] = mn0; mx[mt][1] = mn1;
            float rs0 = 0.f, rs1 = 0.f;
#pragma unroll
            for (int nt = 0; nt < 8; ++nt) {
                sc[mt][nt][0] = exp2f(sc[mt][nt][0] - mn0);
                sc[mt][nt][1] = exp2f(sc[mt][nt][1] - mn0);
                sc[mt][nt][2] = exp2f(sc[mt][nt][2] - mn1);
                sc[mt][nt][3] = exp2f(sc[mt][nt][3] - mn1);
                rs0 += sc[mt][nt][0] + sc[mt][nt][1];
                rs1 += sc[mt][nt][2] + sc[mt][nt][3];
            }
#pragma unroll
            for (int w = 1; w < 4; w <<= 1) {
                rs0 += __shfl_xor_sync(0xffffffffu, rs0, w);
                rs1 += __shfl_xor_sync(0xffffffffu, rs1, w);
            }
            lsum[mt][0] = lsum[mt][0] * c0 + rs0;
            lsum[mt][1] = lsum[mt][1] * c1 + rs1;
#pragma unroll
            for (int nt = 0; nt < 8; ++nt) {
                o[mt][nt][0] *= c0; o[mt][nt][1] *= c0;
                o[mt][nt][2] *= c1; o[mt][nt][3] *= c1;
            }
        }

#pragma unroll
        for (int j = 0; j < 4; ++j) {
            uint32_t ph[2][4];
#pragma unroll
            for (int mt = 0; mt < 2; ++mt) {
                ph[mt][0] = pack_pair_h(sc[mt][2 * j][0],     sc[mt][2 * j][1]);
                ph[mt][1] = pack_pair_h(sc[mt][2 * j][2],     sc[mt][2 * j][3]);
                ph[mt][2] = pack_pair_h(sc[mt][2 * j + 1][0], sc[mt][2 * j + 1][1]);
                ph[mt][3] = pack_pair_h(sc[mt][2 * j + 1][2], sc[mt][2 * j + 1][3]);
            }
            uint32_t vf[8][2];
#pragma unroll
            for (int p = 0; p < 4; ++p) {
                uint32_t ar = (j * 16 + v_roff) * ATT_ROWB + (p * 16 + v_coff) * 2;
                ldsm_x4_t(vf[2 * p][0], vf[2 * p][1], vf[2 * p + 1][0], vf[2 * p + 1][1],
                          kbase + KV_TILE_B + ar);
            }
#pragma unroll
            for (int mt = 0; mt < 2; ++mt)
#pragma unroll
                for (int nt = 0; nt < 8; ++nt)
                    mma_f16(o[mt][nt], ph[mt], vf[nt]);
        }
        __syncthreads();
    }

#pragma unroll
    for (int mt = 0; mt < 2; ++mt) {
        const float inv0 = 1.f / lsum[mt][0], inv1 = 1.f / lsum[mt][1];
        const int gr0 = qb * 128 + wid * 32 + mt * 16 + (lane >> 2);
        const size_t row0 = (tok0 + gr0) * D_MODEL;
        const size_t row1 = (tok0 + gr0 + 8) * D_MODEL;
        const int colb = h * DH + (lane & 3) * 2;
#pragma unroll
        for (int nt = 0; nt < 8; ++nt) {
            int c = colb + nt * 8;
            *reinterpret_cast<uint32_t*>(&ao_h[row0 + c]) =
                pack_pair_h(o[mt][nt][0] * inv0, o[mt][nt][1] * inv0);
            *reinterpret_cast<uint32_t*>(&ao_h[row1 + c]) =
                pack_pair_h(o[mt][nt][2] * inv1, o[mt][nt][3] * inv1);
        }
    }
}

// ---------------------------------------------------------------------------
extern "C" void kernel_launch(void* const* d_in, const int* in_sizes, int n_in,
                              void* d_out, int out_size)
{
    (void)in_sizes; (void)n_in; (void)out_size;
    const float* x     = (const float*)d_in[0];
    const float* w_qkv = (const float*)d_in[1];
    const float* w_out = (const float*)d_in[2];
    const float* b_out = (const float*)d_in[3];
    float* out = (float*)d_out;

    uint16_t *xh, *wq, *qkvh, *aoh, *woh;
    cudaGetSymbolAddress((void**)&xh,  g_x_h);
    cudaGetSymbolAddress((void**)&wq,  g_wqkv_h);
    cudaGetSymbolAddress((void**)&qkvh, g_qkv_h);
    cudaGetSymbolAddress((void**)&aoh, g_ao_h);
    cudaGetSymbolAddress((void**)&woh, g_wout_h);

    cudaFuncSetAttribute((gemm_mma<false, true>),
                         cudaFuncAttributeMaxDynamicSharedMemorySize, G_SMEM);
    cudaFuncSetAttribute((gemm_mma<true, false>),
                         cudaFuncAttributeMaxDynamicSharedMemorySize, G_SMEM);
    cudaFuncSetAttribute(flash_attn_mma,
                         cudaFuncAttributeMaxDynamicSharedMemorySize, ATT_SMEM);

    // 1) pack inputs -> fp16 single
    {
        int n4 = M_TOK * D_MODEL / 4;
        pack_h16<<<(n4 + 255) / 256, 256>>>(x, xh, n4);
        n4 = QKV_LD * D_MODEL / 4;
        pack_h16<<<(n4 + 255) / 256, 256>>>(w_qkv, wq, n4);
        n4 = D_MODEL * D_MODEL / 4;
        pack_h16<<<(n4 + 255) / 256, 256>>>(w_out, woh, n4);
    }

    // 2) QKV projection -> qkv fp16
    //    gemm_mma<HAS_BIAS,SPLIT_OUT>(A, B, bias, C, Ch, M, N, K)
    gemm_mma<false, true><<<dim3(QKV_LD / 128, M_TOK / 128), 128, G_SMEM>>>(
        xh, wq, nullptr, nullptr, qkvh, M_TOK, QKV_LD, D_MODEL);

    // 3) causal flash attention -> ao fp16
    flash_attn_mma<<<dim3(S_LEN / 128, 2 * H_NUM), 128, ATT_SMEM>>>(qkvh, aoh);

    // 4) output projection + bias -> fp32 out
    gemm_mma<true, false><<<dim3(D_MODEL / 128, M_TOK / 128), 128, G_SMEM>>>(
        aoh, woh, b_out, out, nullptr, M_TOK, D_MODEL, D_MODEL);
}

// round 17
// speedup vs baseline: 1.0005x; 1.0005x over previous
#include <cuda_runtime.h>
#include <cuda_fp16.h>
#include <cstdint>
#include <cstddef>

#define S_LEN   2048
#define D_MODEL 1024
#define H_NUM   16
#define DH      64
#define M_TOK   4096
#define QKV_LD  3072

// ---------------------------------------------------------------------------
// Device scratch (fp16 words)
// ---------------------------------------------------------------------------
__device__ uint16_t g_x_h   [(size_t)M_TOK * D_MODEL];
__device__ uint16_t g_wqkv_h[(size_t)QKV_LD * D_MODEL];
__device__ uint16_t g_qkv_h [(size_t)M_TOK * QKV_LD];
__device__ uint16_t g_ao_h  [(size_t)M_TOK * D_MODEL];
__device__ uint16_t g_wout_h[(size_t)D_MODEL * D_MODEL];

// ---------------------------------------------------------------------------
// PTX helpers
// ---------------------------------------------------------------------------
__device__ __forceinline__ uint32_t smem_u32(const void* p) {
    uint32_t a;
    asm("{ .reg .u64 t; cvta.to.shared.u64 t, %1; cvt.u32.u64 %0, t; }" : "=r"(a) : "l"(p));
    return a;
}
__device__ __forceinline__ void cp_async16(uint32_t dst, const void* src) {
    asm volatile("cp.async.cg.shared.global [%0], [%1], 16;" :: "r"(dst), "l"(src));
}
__device__ __forceinline__ void cp_commit() {
    asm volatile("cp.async.commit_group;" ::: "memory");
}
template <int N>
__device__ __forceinline__ void cp_wait() {
    asm volatile("cp.async.wait_group %0;" :: "n"(N) : "memory");
}
__device__ __forceinline__ void ldsm_x4(uint32_t& r0, uint32_t& r1, uint32_t& r2,
                                        uint32_t& r3, uint32_t a) {
    asm volatile("ldmatrix.sync.aligned.m8n8.x4.shared.b16 {%0,%1,%2,%3}, [%4];"
                 : "=r"(r0), "=r"(r1), "=r"(r2), "=r"(r3) : "r"(a));
}
__device__ __forceinline__ void ldsm_x4_t(uint32_t& r0, uint32_t& r1, uint32_t& r2,
                                          uint32_t& r3, uint32_t a) {
    asm volatile("ldmatrix.sync.aligned.m8n8.x4.trans.shared.b16 {%0,%1,%2,%3}, [%4];"
                 : "=r"(r0), "=r"(r1), "=r"(r2), "=r"(r3) : "r"(a));
}
__device__ __forceinline__ void mma_f16(float* d, const uint32_t* a, const uint32_t* b) {
    asm volatile("mma.sync.aligned.m16n8k16.row.col.f32.f16.f16.f32 "
                 "{%0,%1,%2,%3}, {%4,%5,%6,%7}, {%8,%9}, {%0,%1,%2,%3};"
                 : "+f"(d[0]), "+f"(d[1]), "+f"(d[2]), "+f"(d[3])
                 : "r"(a[0]), "r"(a[1]), "r"(a[2]), "r"(a[3]), "r"(b[0]), "r"(b[1]));
}
__device__ __forceinline__ uint32_t pack_pair_h(float a, float b) {
    return (uint32_t)__half_as_ushort(__float2half_rn(a)) |
           ((uint32_t)__half_as_ushort(__float2half_rn(b)) << 16);
}

// ---------------------------------------------------------------------------
// Packer
// ---------------------------------------------------------------------------
__global__ __launch_bounds__(256) void pack_h16(
    const float* __restrict__ in, uint16_t* __restrict__ hi, int n4)
{
    int i = blockIdx.x * 256 + threadIdx.x;
    if (i >= n4) return;
    float4 v = reinterpret_cast<const float4*>(in)[i];
    reinterpret_cast<uint2*>(hi)[i] =
        make_uint2(pack_pair_h(v.x, v.y), pack_pair_h(v.z, v.w));
}

// ---------------------------------------------------------------------------
// HMMA fp16 GEMM: C[M,N] = A @ B^T (+bias), single-pass fp16.
// CTA 256x128, BK=64, 8 warps (4x2), warp tile 64x64, 2-stage cp.async.
// smem/stage: A(256x72) 36864 + B(128x72) 18432 = 55296; 2 stages = 110592
// -> 2 CTAs/SM (221 KB smem, 52K regs) = 16 warps/SM.
// ---------------------------------------------------------------------------
#define BK        64
#define PAD_K     72
#define TILE_A_SMB (256 * PAD_K * 2)     // 36864 B
#define TILE_B_SMB (128 * PAD_K * 2)     // 18432 B
#define STAGE_B    (TILE_A_SMB + TILE_B_SMB)  // 55296 B
#define G_SMEM     (2 * STAGE_B)         // 110592 B

template <bool HAS_BIAS, bool SPLIT_OUT>
__global__ __launch_bounds__(256) void gemm_mma(
    const uint16_t* __restrict__ A, const uint16_t* __restrict__ B,
    const float* __restrict__ bias, float* __restrict__ C,
    uint16_t* __restrict__ Ch,
    int M, int N, int K)
{
    extern __shared__ char smem[];
    const uint32_t sb = smem_u32(smem);
    const int tid = threadIdx.x;
    const int wid = tid >> 5;
    const int lane = tid & 31;
    const int bm = blockIdx.y * 256;
    const int bn = blockIdx.x * 128;
    const int wm = wid >> 1;             // 0..3 -> rows wm*64
    const int wn = wid & 1;              // 0..1 -> cols wn*64
    const int nk = K / BK;

    const uint16_t* gA = A + (size_t)bm * K;
    const uint16_t* gB = B + (size_t)bn * K;

    auto load_stage = [&](int s, int k0) {
        uint32_t base = sb + s * STAGE_B;
        // A: 256 rows x 64 = 2048 16B-chunks; 256 thr x 8
#pragma unroll
        for (int it = 0; it < 8; ++it) {
            int c = tid + it * 256;
            int r = c >> 3, col = (c & 7) * 8;
            cp_async16(base + r * (PAD_K * 2) + col * 2, gA + (size_t)r * K + k0 + col);
        }
        // B: 128 rows x 64 = 1024 chunks; 256 thr x 4
        uint32_t bb = base + TILE_A_SMB;
#pragma unroll
        for (int it = 0; it < 4; ++it) {
            int c = tid + it * 256;
            int r = c >> 3, col = (c & 7) * 8;
            cp_async16(bb + r * (PAD_K * 2) + col * 2, gB + (size_t)r * K + k0 + col);
        }
        cp_commit();
    };

    float acc[4][8][4];
#pragma unroll
    for (int mt = 0; mt < 4; ++mt)
#pragma unroll
        for (int nt = 0; nt < 8; ++nt)
#pragma unroll
            for (int e = 0; e < 4; ++e) acc[mt][nt][e] = 0.f;

    const int lrow8 = lane & 7;
    const int lq    = lane >> 3;
    const int a_roff = lrow8 + (lq & 1) * 8;
    const int a_coff = (lq >> 1) * 8;
    const int b_noff = lrow8 + (lq >> 1) * 8;
    const int b_coff = (lq & 1) * 8;

    load_stage(0, 0);

    for (int i = 0; i < nk; ++i) {
        const int s = i & 1;
        if (i + 1 < nk) { load_stage(s ^ 1, (i + 1) * BK); cp_wait<1>(); }
        else            { cp_wait<0>(); }
        __syncthreads();

        const uint32_t stg = sb + s * STAGE_B;
#pragma unroll
        for (int kk = 0; kk < BK; kk += 16) {
            uint32_t bh[8][2];
#pragma unroll
            for (int ntp = 0; ntp < 4; ++ntp) {
                int nidx = wn * 64 + ntp * 16 + b_noff;
                int cidx = kk + b_coff;
                ldsm_x4(bh[2 * ntp][0], bh[2 * ntp][1], bh[2 * ntp + 1][0], bh[2 * ntp + 1][1],
                        stg + TILE_A_SMB + (nidx * PAD_K + cidx) * 2);
            }
#pragma unroll
            for (int mt = 0; mt < 4; ++mt) {
                int midx = wm * 64 + mt * 16 + a_roff;
                int cidx = kk + a_coff;
                uint32_t ah[4];
                ldsm_x4(ah[0], ah[1], ah[2], ah[3], stg + (midx * PAD_K + cidx) * 2);
#pragma unroll
                for (int nt = 0; nt < 8; ++nt)
                    mma_f16(acc[mt][nt], ah, bh[nt]);
            }
        }
        __syncthreads();
    }

#pragma unroll
    for (int mt = 0; mt < 4; ++mt) {
#pragma unroll
        for (int nt = 0; nt < 8; ++nt) {
            int r = bm + wm * 64 + mt * 16 + (lane >> 2);
            int c = bn + wn * 64 + nt * 8 + (lane & 3) * 2;
            if (SPLIT_OUT) {
                *reinterpret_cast<uint32_t*>(&Ch[(size_t)r * N + c]) =
                    pack_pair_h(acc[mt][nt][0], acc[mt][nt][1]);
                *reinterpret_cast<uint32_t*>(&Ch[(size_t)(r + 8) * N + c]) =
                    pack_pair_h(acc[mt][nt][2], acc[mt][nt][3]);
            } else {
                float b0 = 0.f, b1 = 0.f;
                if (HAS_BIAS) { b0 = bias[c]; b1 = bias[c + 1]; }
                *reinterpret_cast<float2*>(&C[(size_t)r * N + c]) =
                    make_float2(acc[mt][nt][0] + b0, acc[mt][nt][1] + b1);
                *reinterpret_cast<float2*>(&C[(size_t)(r + 8) * N + c]) =
                    make_float2(acc[mt][nt][2] + b0, acc[mt][nt][3] + b1);
            }
        }
    }
}

// ---------------------------------------------------------------------------
// fp16 causal flash attention, 32 q-rows per warp (unchanged from R16).
// CTA: 128 q-rows x (b,h), 4 warps. Bc=64. 3-stage KV pipeline. exp2 softmax.
// ---------------------------------------------------------------------------
#define ATT_PAD    72
#define ATT_ROWB   (ATT_PAD * 2)          // 144 B
#define KV_TILE_B  (64 * ATT_ROWB)        // 9216
#define ATT_STAGE  (2 * KV_TILE_B)        // 18432 (K, V)
#define ATT_SMEM   (3 * ATT_STAGE)        // 55296

#define SCALE_LOG2 (0.125f * 1.4426950408889634f)

__global__ __launch_bounds__(128) void flash_attn_mma(
    const uint16_t* __restrict__ qkv_h, uint16_t* __restrict__ ao_h)
{
    extern __shared__ char smem[];
    const uint32_t sb = smem_u32(smem);
    const int tid = threadIdx.x, wid = tid >> 5, lane = tid & 31;
    const int qb = 15 - blockIdx.x;
    const int bh = blockIdx.y;
    const int b = bh >> 4, h = bh & 15;
    const size_t tok0 = (size_t)b * S_LEN;

    const int lrow8 = lane & 7, lq = lane >> 3;
    const int a_roff = lrow8 + (lq & 1) * 8;
    const int a_coff = (lq >> 1) * 8;
    const int b_noff = lrow8 + (lq >> 1) * 8;
    const int b_coff = (lq & 1) * 8;
    const int v_roff = (lane & 7) + ((lane >> 3) & 1) * 8;
    const int v_coff = (lane >> 4) * 8;

    {
        const size_t qrow0 = tok0 + (size_t)qb * 128;
#pragma unroll
        for (int it = 0; it < 8; ++it) {
            int c = tid + it * 128;
            int r = c >> 3, col = (c & 7) * 8;
            cp_async16(sb + r * ATT_ROWB + col * 2,
                       qkv_h + (qrow0 + r) * QKV_LD + h * 192 + col);
        }
        cp_commit();
        cp_wait<0>();
        __syncthreads();
    }
    uint32_t qh[2][4][4];
#pragma unroll
    for (int mt = 0; mt < 2; ++mt)
#pragma unroll
        for (int j = 0; j < 4; ++j) {
            int rr = wid * 32 + mt * 16 + a_roff;
            int cc = j * 16 + a_coff;
            ldsm_x4(qh[mt][j][0], qh[mt][j][1], qh[mt][j][2], qh[mt][j][3],
                    sb + rr * ATT_ROWB + cc * 2);
        }
    __syncthreads();

    auto load_kv = [&](int s, int kb) {
        uint32_t base = sb + s * ATT_STAGE;
        const size_t krow0 = tok0 + (size_t)kb * 64;
        const int koff = h * 192 + 64, voff = h * 192 + 128;
#pragma unroll
        for (int it = 0; it < 4; ++it) {
            int c = tid + it * 128;
            int r = c >> 3, col = (c & 7) * 8;
            const size_t go = (krow0 + r) * QKV_LD + col;
            cp_async16(base + r * ATT_ROWB + col * 2, qkv_h + go + koff);
            cp_async16(base + KV_TILE_B + r * ATT_ROWB + col * 2, qkv_h + go + voff);
        }
        cp_commit();
    };

    float o[2][8][4];
#pragma unroll
    for (int mt = 0; mt < 2; ++mt)
#pragma unroll
        for (int nt = 0; nt < 8; ++nt)
#pragma unroll
            for (int e = 0; e < 4; ++e) o[mt][nt][e] = 0.f;
    float mx[2][2], lsum[2][2];
#pragma unroll
    for (int mt = 0; mt < 2; ++mt) {
        mx[mt][0] = -1e30f; mx[mt][1] = -1e30f;
        lsum[mt][0] = 0.f;  lsum[mt][1] = 0.f;
    }

    const int nkb = 2 * qb + 2;
    load_kv(0, 0);
    if (nkb > 1) load_kv(1, 1);

    for (int kb = 0; kb < nkb; ++kb) {
        const int s = kb % 3;
        if (kb + 2 < nkb) { load_kv((kb + 2) % 3, kb + 2); cp_wait<2>(); }
        else if (kb + 1 < nkb) { cp_wait<1>(); }
        else { cp_wait<0>(); }
        __syncthreads();
        const uint32_t kbase = sb + s * ATT_STAGE;

        float sc[2][8][4];
#pragma unroll
        for (int mt = 0; mt < 2; ++mt)
#pragma unroll
            for (int nt = 0; nt < 8; ++nt)
#pragma unroll
                for (int e = 0; e < 4; ++e) sc[mt][nt][e] = 0.f;

#pragma unroll
        for (int j = 0; j < 4; ++j) {
            uint32_t kf[8][2];
#pragma unroll
            for (int p = 0; p < 4; ++p) {
                int nn = p * 16 + b_noff;
                int cc = j * 16 + b_coff;
                ldsm_x4(kf[2 * p][0], kf[2 * p][1], kf[2 * p + 1][0], kf[2 * p + 1][1],
                        kbase + nn * ATT_ROWB + cc * 2);
            }
#pragma unroll
            for (int mt = 0; mt < 2; ++mt)
#pragma unroll
                for (int nt = 0; nt < 8; ++nt)
                    mma_f16(sc[mt][nt], qh[mt][j], kf[nt]);
        }

#pragma unroll
        for (int mt = 0; mt < 2; ++mt)
#pragma unroll
            for (int nt = 0; nt < 8; ++nt)
#pragma unroll
                for (int e = 0; e < 4; ++e) sc[mt][nt][e] *= SCALE_LOG2;

        if (kb >= 2 * qb) {
#pragma unroll
            for (int mt = 0; mt < 2; ++mt) {
                const int gr0 = qb * 128 + wid * 32 + mt * 16 + (lane >> 2);
#pragma unroll
                for (int nt = 0; nt < 8; ++nt) {
                    int gc = kb * 64 + nt * 8 + (lane & 3) * 2;
                    if (gc     > gr0)     sc[mt][nt][0] = -1e30f;
                    if (gc + 1 > gr0)     sc[mt][nt][1] = -1e30f;
                    if (gc     > gr0 + 8) sc[mt][nt][2] = -1e30f;
                    if (gc + 1 > gr0 + 8) sc[mt][nt][3] = -1e30f;
                }
            }
        }

#pragma unroll
        for (int mt = 0; mt < 2; ++mt) {
            float mx0 = -1e30f, mx1 = -1e30f;
#pragma unroll
            for (int nt = 0; nt < 8; ++nt) {
                mx0 = fmaxf(mx0, fmaxf(sc[mt][nt][0], sc[mt][nt][1]));
                mx1 = fmaxf(mx1, fmaxf(sc[mt][nt][2], sc[mt][nt][3]));
            }
#pragma unroll
            for (int w = 1; w < 4; w <<= 1) {
                mx0 = fmaxf(mx0, __shfl_xor_sync(0xffffffffu, mx0, w));
                mx1 = fmaxf(mx1, __shfl_xor_sync(0xffffffffu, mx1, w));
            }
            float mn0 = fmaxf(mx[mt][0], mx0), mn1 = fmaxf(mx[mt][1], mx1);
            float c0 = exp2f(mx[mt][0] - mn0), c1 = exp2f(mx[mt][1] - mn1);
            mx[mt][0] = mn0; mx[mt][1] = mn1;
            float rs0 = 0.f, rs1 = 0.f;
#pragma unroll
            for (int nt = 0; nt < 8; ++nt) {
                sc[mt][nt][0] = exp2f(sc[mt][nt][0] - mn0);
                sc[mt][nt][1] = exp2f(sc[mt][nt][1] - mn0);
                sc[mt][nt][2] = exp2f(sc[mt][nt][2] - mn1);
                sc[mt][nt][3] = exp2f(sc[mt][nt][3] - mn1);
                rs0 += sc[mt][nt][0] + sc[mt][nt][1];
                rs1 += sc[mt][nt][2] + sc[mt][nt][3];
            }
#pragma unroll
            for (int w = 1; w < 4; w <<= 1) {
                rs0 += __shfl_xor_sync(0xffffffffu, rs0, w);
                rs1 += __shfl_xor_sync(0xffffffffu, rs1, w);
            }
            lsum[mt][0] = lsum[mt][0] * c0 + rs0;
            lsum[mt][1] = lsum[mt][1] * c1 + rs1;
#pragma unroll
            for (int nt = 0; nt < 8; ++nt) {
                o[mt][nt][0] *= c0; o[mt][nt][1] *= c0;
                o[mt][nt][2] *= c1; o[mt][nt][3] *= c1;
            }
        }

#pragma unroll
        for (int j = 0; j < 4; ++j) {
            uint32_t ph[2][4];
#pragma unroll
            for (int mt = 0; mt < 2; ++mt) {
                ph[mt][0] = pack_pair_h(sc[mt][2 * j][0],     sc[mt][2 * j][1]);
                ph[mt][1] = pack_pair_h(sc[mt][2 * j][2],     sc[mt][2 * j][3]);
                ph[mt][2] = pack_pair_h(sc[mt][2 * j + 1][0], sc[mt][2 * j + 1][1]);
                ph[mt][3] = pack_pair_h(sc[mt][2 * j + 1][2], sc[mt][2 * j + 1][3]);
            }
            uint32_t vf[8][2];
#pragma unroll
            for (int p = 0; p < 4; ++p) {
                uint32_t ar = (j * 16 + v_roff) * ATT_ROWB + (p * 16 + v_coff) * 2;
                ldsm_x4_t(vf[2 * p][0], vf[2 * p][1], vf[2 * p + 1][0], vf[2 * p + 1][1],
                          kbase + KV_TILE_B + ar);
            }
#pragma unroll
            for (int mt = 0; mt < 2; ++mt)
#pragma unroll
                for (int nt = 0; nt < 8; ++nt)
                    mma_f16(o[mt][nt], ph[mt], vf[nt]);
        }
        __syncthreads();
    }

#pragma unroll
    for (int mt = 0; mt < 2; ++mt) {
        const float inv0 = 1.f / lsum[mt][0], inv1 = 1.f / lsum[mt][1];
        const int gr0 = qb * 128 + wid * 32 + mt * 16 + (lane >> 2);
        const size_t row0 = (tok0 + gr0) * D_MODEL;
        const size_t row1 = (tok0 + gr0 + 8) * D_MODEL;
        const int colb = h * DH + (lane & 3) * 2;
#pragma unroll
        for (int nt = 0; nt < 8; ++nt) {
            int c = colb + nt * 8;
            *reinterpret_cast<uint32_t*>(&ao_h[row0 + c]) =
                pack_pair_h(o[mt][nt][0] * inv0, o[mt][nt][1] * inv0);
            *reinterpret_cast<uint32_t*>(&ao_h[row1 + c]) =
                pack_pair_h(o[mt][nt][2] * inv1, o[mt][nt][3] * inv1);
        }
    }
}

// ---------------------------------------------------------------------------
extern "C" void kernel_launch(void* const* d_in, const int* in_sizes, int n_in,
                              void* d_out, int out_size)
{
    (void)in_sizes; (void)n_in; (void)out_size;
    const float* x     = (const float*)d_in[0];
    const float* w_qkv = (const float*)d_in[1];
    const float* w_out = (const float*)d_in[2];
    const float* b_out = (const float*)d_in[3];
    float* out = (float*)d_out;

    uint16_t *xh, *wq, *qkvh, *aoh, *woh;
    cudaGetSymbolAddress((void**)&xh,  g_x_h);
    cudaGetSymbolAddress((void**)&wq,  g_wqkv_h);
    cudaGetSymbolAddress((void**)&qkvh, g_qkv_h);
    cudaGetSymbolAddress((void**)&aoh, g_ao_h);
    cudaGetSymbolAddress((void**)&woh, g_wout_h);

    cudaFuncSetAttribute((gemm_mma<false, true>),
                         cudaFuncAttributeMaxDynamicSharedMemorySize, G_SMEM);
    cudaFuncSetAttribute((gemm_mma<true, false>),
                         cudaFuncAttributeMaxDynamicSharedMemorySize, G_SMEM);
    cudaFuncSetAttribute(flash_attn_mma,
                         cudaFuncAttributeMaxDynamicSharedMemorySize, ATT_SMEM);

    // 1) pack inputs -> fp16 single
    {
        int n4 = M_TOK * D_MODEL / 4;
        pack_h16<<<(n4 + 255) / 256, 256>>>(x, xh, n4);
        n4 = QKV_LD * D_MODEL / 4;
        pack_h16<<<(n4 + 255) / 256, 256>>>(w_qkv, wq, n4);
        n4 = D_MODEL * D_MODEL / 4;
        pack_h16<<<(n4 + 255) / 256, 256>>>(w_out, woh, n4);
    }

    // 2) QKV projection -> qkv fp16  (CTA tile 256x128)
    //    gemm_mma<HAS_BIAS,SPLIT_OUT>(A, B, bias, C, Ch, M, N, K)
    gemm_mma<false, true><<<dim3(QKV_LD / 128, M_TOK / 256), 256, G_SMEM>>>(
        xh, wq, nullptr, nullptr, qkvh, M_TOK, QKV_LD, D_MODEL);

    // 3) causal flash attention -> ao fp16
    flash_attn_mma<<<dim3(S_LEN / 128, 2 * H_NUM), 128, ATT_SMEM>>>(qkvh, aoh);

    // 4) output projection + bias -> fp32 out
    gemm_mma<true, false><<<dim3(D_MODEL / 128, M_TOK / 256), 256, G_SMEM>>>(
        aoh, woh, b_out, out, nullptr, M_TOK, D_MODEL, D_MODEL);
}